// round 5
// baseline (speedup 1.0000x reference)
#include <cuda_runtime.h>
#include <cuda_bf16.h>

// OntologyNN: K=8 complete tree, DEPTH=5. NUM_NODES=37449.
// leaves [4681,37449), L4 parents [585,4681), L3 [73,585), L2 [9,73), L1 [1,9), root 0.
// out[b][p] = clamp(sum_k sigmoid(w[8p+1+k]) * val(8p+1+k), 0, 1); leaves pass through.

#define NODES      37449
#define BATCHN     2048
#define LEAF_START 4681
#define L4_START   585
#define TPB        256
#define NWARP      8
#define SWSTRIDE   37460   // >= NODES+8, multiple of 4 (each copy 16B-aligned)

// 4 shifted copies of sigmoid(w): g_sw4[c][j] = sigmoid(w[j+c]).
__device__ __align__(16) float g_sw4[4][SWSTRIDE];

__global__ void sigmoid_kernel(const float* __restrict__ w) {
    int i = blockIdx.x * blockDim.x + threadIdx.x;
    if (i < NODES + 8) {
        float s = 0.0f;
        if (i < NODES) s = 1.0f / (1.0f + expf(-w[i]));
        #pragma unroll
        for (int c = 0; c < 4; ++c) {
            int j = i - c;
            if (j >= 0) g_sw4[c][j] = s;
        }
    }
}

__device__ __forceinline__ float clamp01(float v) {
    return fminf(fmaxf(v, 0.0f), 1.0f);
}

__global__ void __launch_bounds__(TPB, 8) tree_kernel(const float* __restrict__ in,
                                                      float* __restrict__ out) {
    __shared__ float internal[LEAF_START];   // nodes 0..4680 for this row

    const int b = blockIdx.x;
    const long long row = (long long)b * NODES;
    const float* __restrict__ inr  = in  + row;
    float*       __restrict__ outr = out + row;
    const int tid  = threadIdx.x;
    const int lane = tid & 31;
    const int wid  = tid >> 5;

    // Misalignment of leaf base within 16B: (37449*b + 4681) mod 4 == (b+1) mod 4.
    const int a = (b + 1) & 3;
    // Weight copy making (n0 - c) 4-aligned: c == (-b) mod 4.
    const int c = (4 - (b & 3)) & 3;
    const float* __restrict__ swp = g_sw4[c];
    const unsigned F = 0xffffffffu;

    // ---- Phase 1: one warp per 256-leaf window; lane owns one 8-leaf group. ----
    // Window w: leaves [W, W+256) -> parents [585+32w, 585+32w+32), lane l -> parent +l.
    // Cover [W-a, W+256-a) is 16B-aligned; lane l loads cover elems [8l, 8l+8).
    // Group leaves are cover elems [8l+a, 8l+8+a): missing head of lane l+1 -> 1 shfl.
    for (int w = wid; w < 128; w += NWARP) {
        const int W  = w << 8;
        const int ex = LEAF_START + W - a;               // aligned row-relative cover base
        const float4* inx = (const float4*)(inr + ex);
        float4 v0 = inx[2 * lane];
        float4 v1 = inx[2 * lane + 1];

        const int n0 = ex + 8 * lane;                    // node index of v0.x
        const float4* swx = (const float4*)(swp + (n0 - c));
        float4 w0 = swx[0];
        float4 w1 = swx[1];

        // Boundary vector for lane 31 (next window's first float4). Only needed if a != 0.
        // Last batch row has a == 0, so this never reads past the input buffer.
        float4 z, wz;
        if (a != 0 && lane == 31) {
            const int nz = ex + 256;
            z  = *(const float4*)(inr + nz);
            wz = *(const float4*)(swp + (nz - c));
        }

        // Leaf pass-through (aligned STG.128; window overlaps rewrite identical values).
        {
            float4* outx = (float4*)(outr + ex);
            if (w == 0 && lane == 0) {
                // First 'a' cover elems fall in the L4 parent region: mask them
                // (avoids racing the parent stores of another warp).
                const float* vp = (const float*)&v0;
                #pragma unroll
                for (int i = 0; i < 4; ++i)
                    if (i >= a) outr[ex + i] = vp[i];
                outx[1] = v1;
            } else {
                outx[2 * lane]     = v0;
                outx[2 * lane + 1] = v1;
            }
            if (a != 0 && w == 127 && lane == 31) {
                // Tail leaves [32768-a, 32768) only covered by z.
                const float* zp = (const float*)&z;
                #pragma unroll
                for (int i = 0; i < 3; ++i)
                    if (i < a) outr[ex + 256 + i] = zp[i];
            }
        }

        // Products and group sum (uniform path for all a).
        float p0 = v0.x * w0.x, p1 = v0.y * w0.y, p2 = v0.z * w0.z, p3 = v0.w * w0.w;
        float q0 = v1.x * w1.x, q1 = v1.y * w1.y, q2 = v1.z * w1.z, q3 = v1.w * w1.w;
        float full = ((p0 + p1) + (p2 + p3)) + ((q0 + q1) + (q2 + q3));
        float head = 0.0f;
        if (a > 0) head  = p0;
        if (a > 1) head += p1;
        if (a > 2) head += p2;
        float nhead = __shfl_down_sync(F, head, 1);
        if (a != 0 && lane == 31) {
            nhead = z.x * wz.x;
            if (a > 1) nhead += z.y * wz.y;
            if (a > 2) nhead += z.z * wz.z;
        }

        float r = clamp01((full - head) + nhead);
        const int p = L4_START + (w << 5) + lane;        // coalesced 128B store
        internal[p] = r;
        outr[p] = r;
    }
    __syncthreads();

    // ---- Upper levels from shared memory ----
    const float* __restrict__ sw0 = g_sw4[0];            // sw0[j] = sigmoid(w[j])

    // level 3: parents [73, 585)
    for (int j = tid; j < 512; j += TPB) {
        const int p = 73 + j, cc = 8 * p + 1;
        float s = 0.0f;
        #pragma unroll
        for (int k = 0; k < 8; ++k) s += internal[cc + k] * sw0[cc + k];
        float r = clamp01(s);
        internal[p] = r;
        outr[p] = r;
    }
    __syncthreads();

    // level 2: parents [9, 73)
    if (tid < 64) {
        const int p = 9 + tid, cc = 8 * p + 1;
        float s = 0.0f;
        #pragma unroll
        for (int k = 0; k < 8; ++k) s += internal[cc + k] * sw0[cc + k];
        float r = clamp01(s);
        internal[p] = r;
        outr[p] = r;
    }
    __syncthreads();

    // level 1: parents [1, 9)
    if (tid < 8) {
        const int p = 1 + tid, cc = 8 * p + 1;
        float s = 0.0f;
        #pragma unroll
        for (int k = 0; k < 8; ++k) s += internal[cc + k] * sw0[cc + k];
        float r = clamp01(s);
        internal[p] = r;
        outr[p] = r;
    }
    __syncthreads();

    // root
    if (tid == 0) {
        float s = 0.0f;
        #pragma unroll
        for (int k = 1; k <= 8; ++k) s += internal[k] * sw0[k];
        outr[0] = clamp01(s);
    }
}

extern "C" void kernel_launch(void* const* d_in, const int* in_sizes, int n_in,
                              void* d_out, int out_size) {
    const float* probs = (const float*)d_in[0];   // [2048, 37449] fp32
    const float* w     = (const float*)d_in[1];   // [37449] fp32
    float* out = (float*)d_out;                   // [2048, 37449] fp32

    sigmoid_kernel<<<(NODES + 8 + TPB - 1) / TPB, TPB>>>(w);
    tree_kernel<<<BATCHN, TPB>>>(probs, out);
}